// round 8
// baseline (speedup 1.0000x reference)
#include <cuda_runtime.h>

// Problem constants
#define B_   2
#define L_   2048
#define DM   256      // d_model
#define DI   512      // d_inner
#define NS   16       // d_state
#define RK   16       // dt_rank
#define T_   (B_*L_)  // 4096 tokens
#define NC   16       // scan chunks
#define CL   128      // chunk length (NC*CL == L_)
#define ST_  (B_*DI*NS)  // 16384 state slots

// ---------------- scratch (device globals, no allocation) ----------------
__device__ float g_h[T_ * DM];       // layernorm output
__device__ float g_xi[T_ * DI];      // in_proj first half
__device__ float g_z[T_ * DI];       // silu(in_proj second half)
__device__ float g_xc[T_ * DI];      // conv + silu output
__device__ float g_bc[T_ * 32];      // x_proj B|C (16+16)
__device__ float g_delta[T_ * DI];   // softplus(dt @ dpw + dpb)
__device__ float g_y[T_ * DI];       // scan output (post gating)
__device__ float g_x1[T_ * DM];      // inter-layer residual stream
__device__ float g_hloc[NC * ST_];   // chunk-local end state (h_in = 0)
__device__ float g_P[NC * ST_];      // chunk decay products
__device__ float g_hin[NC * ST_];    // carried-in state per chunk

// ---------------- layernorm: one block (256 thr) per token ----------------
__global__ void __launch_bounds__(256) ln_kernel(
    const float* __restrict__ x0, int layer,
    const float* __restrict__ w, const float* __restrict__ b)
{
    const float* xin = layer ? g_x1 : x0;
    int t = blockIdx.x;
    int d = threadIdx.x;
    float v = xin[(size_t)t * DM + d];
    float s = v, s2 = v * v;
#pragma unroll
    for (int m = 16; m; m >>= 1) {
        s  += __shfl_xor_sync(0xffffffffu, s,  m);
        s2 += __shfl_xor_sync(0xffffffffu, s2, m);
    }
    __shared__ float ss[8], ss2[8];
    int wid = d >> 5, ln = d & 31;
    if (ln == 0) { ss[wid] = s; ss2[wid] = s2; }
    __syncthreads();
    float tot = 0.f, tot2 = 0.f;
#pragma unroll
    for (int i = 0; i < 8; i++) { tot += ss[i]; tot2 += ss2[i]; }
    float mu  = tot * (1.f / DM);
    float var = tot2 * (1.f / DM) - mu * mu;
    float r   = rsqrtf(var + 1e-5f);
    g_h[(size_t)t * DM + d] = (v - mu) * r * w[d] + b[d];
}

// ---------------- SGEMM NT: C[m][n] = dot(A[m,:], Bw[n,:]) ----------------
// BM x 128 tile, BK=8, 256 threads, (BM/16) x 8 microtile, float4 smem reads,
// register-staged double buffering.
// EPI 1: in_proj (A = g_h, N=1024): n<512 -> g_xi ; n>=512 -> silu -> g_z
// EPI 2: out_proj + residual (A = g_y, N=256)
template <int BM, int EPI>
__global__ void __launch_bounds__(256) gemm_k(
    const float* __restrict__ Bw, const int K,
    const int layer, const float* __restrict__ x0, float* __restrict__ dout)
{
    constexpr int TM = BM / 16;
    __shared__ float As[2][8][BM];
    __shared__ float Bs[2][8][128];

    const int tid = threadIdx.x;
    const int tx = tid & 15, ty = tid >> 4;
    const int bm = blockIdx.y * BM, bn = blockIdx.x * 128;
    const float* Aq = (EPI == 1) ? g_h : g_y;

    // global->reg load mapping
    int ar, ak;
    if (BM == 128) { ar = tid >> 1; ak = (tid & 1) * 4; }
    else           { ar = tid >> 2; ak = (tid & 3) * 2; }
    const int br = tid >> 1;
    const int bk = (tid & 1) * 4;
    const float* aptr = Aq + (size_t)(bm + ar) * K + ak;
    const float* bptr = Bw + (size_t)(bn + br) * K + bk;

    float acc[TM][8];
#pragma unroll
    for (int i = 0; i < TM; i++)
#pragma unroll
        for (int j = 0; j < 8; j++) acc[i][j] = 0.f;

    float ra[4];
    float4 rb;

    // prefetch k-tile 0
    if (BM == 128) {
        float4 v = *(const float4*)(aptr);
        ra[0] = v.x; ra[1] = v.y; ra[2] = v.z; ra[3] = v.w;
    } else {
        float2 v = *(const float2*)(aptr);
        ra[0] = v.x; ra[1] = v.y;
    }
    rb = *(const float4*)(bptr);
    if (BM == 128) {
        As[0][ak + 0][ar] = ra[0]; As[0][ak + 1][ar] = ra[1];
        As[0][ak + 2][ar] = ra[2]; As[0][ak + 3][ar] = ra[3];
    } else {
        As[0][ak + 0][ar] = ra[0]; As[0][ak + 1][ar] = ra[1];
    }
    Bs[0][bk + 0][br] = rb.x; Bs[0][bk + 1][br] = rb.y;
    Bs[0][bk + 2][br] = rb.z; Bs[0][bk + 3][br] = rb.w;
    __syncthreads();

    const int nt = K / 8;
    int cur = 0;
    for (int kt = 0; kt < nt; kt++) {
        if (kt + 1 < nt) {
            int k0 = (kt + 1) * 8;
            if (BM == 128) {
                float4 v = *(const float4*)(aptr + k0);
                ra[0] = v.x; ra[1] = v.y; ra[2] = v.z; ra[3] = v.w;
            } else {
                float2 v = *(const float2*)(aptr + k0);
                ra[0] = v.x; ra[1] = v.y;
            }
            rb = *(const float4*)(bptr + k0);
        }
#pragma unroll
        for (int kk = 0; kk < 8; kk++) {
            float av[TM], bv[8];
            float4 t0 = *(const float4*)&As[cur][kk][ty * 4];
            av[0] = t0.x; av[1] = t0.y; av[2] = t0.z; av[3] = t0.w;
            if (TM == 8) {
                float4 t1 = *(const float4*)&As[cur][kk][64 + ty * 4];
                av[4] = t1.x; av[5] = t1.y; av[6] = t1.z; av[7] = t1.w;
            }
            float4 u0 = *(const float4*)&Bs[cur][kk][tx * 4];
            float4 u1 = *(const float4*)&Bs[cur][kk][64 + tx * 4];
            bv[0] = u0.x; bv[1] = u0.y; bv[2] = u0.z; bv[3] = u0.w;
            bv[4] = u1.x; bv[5] = u1.y; bv[6] = u1.z; bv[7] = u1.w;
#pragma unroll
            for (int i = 0; i < TM; i++)
#pragma unroll
                for (int j = 0; j < 8; j++)
                    acc[i][j] = fmaf(av[i], bv[j], acc[i][j]);
        }
        if (kt + 1 < nt) {
            int nb = cur ^ 1;
            if (BM == 128) {
                As[nb][ak + 0][ar] = ra[0]; As[nb][ak + 1][ar] = ra[1];
                As[nb][ak + 2][ar] = ra[2]; As[nb][ak + 3][ar] = ra[3];
            } else {
                As[nb][ak + 0][ar] = ra[0]; As[nb][ak + 1][ar] = ra[1];
            }
            Bs[nb][bk + 0][br] = rb.x; Bs[nb][bk + 1][br] = rb.y;
            Bs[nb][bk + 2][br] = rb.z; Bs[nb][bk + 3][br] = rb.w;
            __syncthreads();
            cur = nb;
        }
    }

    // epilogue
#pragma unroll
    for (int i = 0; i < TM; i++) {
        int m;
        if (BM == 128) m = bm + (i >> 2) * 64 + ty * 4 + (i & 3);
        else           m = bm + ty * 4 + i;
        float4 v0, v1;
        v0.x = acc[i][0]; v0.y = acc[i][1]; v0.z = acc[i][2]; v0.w = acc[i][3];
        v1.x = acc[i][4]; v1.y = acc[i][5]; v1.z = acc[i][6]; v1.w = acc[i][7];
        int n0 = bn + tx * 4;
        int n1 = bn + 64 + tx * 4;
        if (EPI == 1) {
            if (bn < 512) {
                *(float4*)&g_xi[(size_t)m * DI + n0] = v0;
                *(float4*)&g_xi[(size_t)m * DI + n1] = v1;
            } else {
                v0.x = v0.x / (1.f + __expf(-v0.x));
                v0.y = v0.y / (1.f + __expf(-v0.y));
                v0.z = v0.z / (1.f + __expf(-v0.z));
                v0.w = v0.w / (1.f + __expf(-v0.w));
                v1.x = v1.x / (1.f + __expf(-v1.x));
                v1.y = v1.y / (1.f + __expf(-v1.y));
                v1.z = v1.z / (1.f + __expf(-v1.z));
                v1.w = v1.w / (1.f + __expf(-v1.w));
                *(float4*)&g_z[(size_t)m * DI + (n0 - 512)] = v0;
                *(float4*)&g_z[(size_t)m * DI + (n1 - 512)] = v1;
            }
        } else {
            const float* res = layer ? g_x1 : x0;
            float*       o   = layer ? dout : g_x1;
            float4 r0 = *(const float4*)&res[(size_t)m * DM + n0];
            float4 r1 = *(const float4*)&res[(size_t)m * DM + n1];
            v0.x += r0.x; v0.y += r0.y; v0.z += r0.z; v0.w += r0.w;
            v1.x += r1.x; v1.y += r1.y; v1.z += r1.z; v1.w += r1.w;
            *(float4*)&o[(size_t)m * DM + n0] = v0;
            *(float4*)&o[(size_t)m * DM + n1] = v1;
        }
    }
}

// ---------------- depthwise causal conv (k=4) + bias + silu ----------------
__global__ void __launch_bounds__(256) conv_silu_kernel(
    const float* __restrict__ cw, const float* __restrict__ cb)
{
    int idx = blockIdx.x * blockDim.x + threadIdx.x;   // over T_*DI
    int e = idx & (DI - 1);
    int t = idx >> 9;
    int l = t & (L_ - 1);
    float acc = cb[e];
    float w0 = cw[e * 4 + 0], w1 = cw[e * 4 + 1];
    float w2 = cw[e * 4 + 2], w3 = cw[e * 4 + 3];
    const float* base = g_xi + (size_t)t * DI + e;
    if (l >= 3) acc = fmaf(w0, base[-3 * DI], acc);
    if (l >= 2) acc = fmaf(w1, base[-2 * DI], acc);
    if (l >= 1) acc = fmaf(w2, base[-1 * DI], acc);
    acc = fmaf(w3, base[0], acc);
    g_xc[idx] = acc / (1.f + __expf(-acc));
}

// ---------------- fused x_proj (N=48) + delta --------------------------
// One block = 16 tokens. Stage 1: xc tile -> smem. Stage 2: dbl = xc @ xpw^T
// (2n x 2tok register blocking). Stage 3: delta = softplus(dt @ dpw^T + dpb).
#define XT 16
__global__ void __launch_bounds__(256) xproj_delta_kernel(
    const float* __restrict__ xpw,   // [48][512]
    const float* __restrict__ dpw,   // [512][16]
    const float* __restrict__ dpb)   // [512]
{
    __shared__ float xs[XT][DI];     // 32 KB
    __shared__ float ws[64][49];     // transposed weight chunk (padded)
    __shared__ float ds[XT][RK];     // dt
    const int tid = threadIdx.x;
    const int t0 = blockIdx.x * XT;

    // stage 1
    {
        const float4* src = (const float4*)(g_xc + (size_t)t0 * DI);
        float4* dst = (float4*)(&xs[0][0]);
#pragma unroll
        for (int i = 0; i < 8; i++) dst[tid + 256 * i] = src[tid + 256 * i];
    }
    __syncthreads();

    // stage 2
    const int ng = tid % 24;
    const int tg = tid / 24;
    const bool act = tg < 8;
    const int n0 = ng * 2, ta = tg * 2, tb = ta + 1;
    float a00 = 0.f, a01 = 0.f, a10 = 0.f, a11 = 0.f;

    for (int k0 = 0; k0 < DI; k0 += 64) {
#pragma unroll
        for (int j = 0; j < 3; j++) {
            int f = tid + 256 * j;
            int n = f >> 4, kk = (f & 15) * 4;
            float4 w4 = *(const float4*)(xpw + (size_t)n * DI + k0 + kk);
            ws[kk + 0][n] = w4.x; ws[kk + 1][n] = w4.y;
            ws[kk + 2][n] = w4.z; ws[kk + 3][n] = w4.w;
        }
        __syncthreads();
        if (act) {
#pragma unroll 16
            for (int k = 0; k < 64; k++) {
                float w0 = ws[k][n0], w1 = ws[k][n0 + 1];
                float xa = xs[ta][k0 + k], xb = xs[tb][k0 + k];
                a00 = fmaf(w0, xa, a00);
                a01 = fmaf(w1, xa, a01);
                a10 = fmaf(w0, xb, a10);
                a11 = fmaf(w1, xb, a11);
            }
        }
        __syncthreads();
    }
    if (act) {
        if (n0 < RK) { ds[ta][n0] = a00; ds[tb][n0] = a10; }
        else { g_bc[(size_t)(t0 + ta) * 32 + n0 - RK] = a00;
               g_bc[(size_t)(t0 + tb) * 32 + n0 - RK] = a10; }
        int n1 = n0 + 1;
        if (n1 < RK) { ds[ta][n1] = a01; ds[tb][n1] = a11; }
        else { g_bc[(size_t)(t0 + ta) * 32 + n1 - RK] = a01;
               g_bc[(size_t)(t0 + tb) * 32 + n1 - RK] = a11; }
    }
    __syncthreads();

    // stage 3: delta for e0 = tid, e1 = tid + 256
    const int e0 = tid, e1 = tid + 256;
    float w0r[16], w1r[16];
#pragma unroll
    for (int q = 0; q < 4; q++) {
        float4 v = *(const float4*)(dpw + (size_t)e0 * RK + q * 4);
        w0r[q * 4 + 0] = v.x; w0r[q * 4 + 1] = v.y;
        w0r[q * 4 + 2] = v.z; w0r[q * 4 + 3] = v.w;
        float4 u = *(const float4*)(dpw + (size_t)e1 * RK + q * 4);
        w1r[q * 4 + 0] = u.x; w1r[q * 4 + 1] = u.y;
        w1r[q * 4 + 2] = u.z; w1r[q * 4 + 3] = u.w;
    }
    float b0 = dpb[e0], b1 = dpb[e1];
#pragma unroll
    for (int tok = 0; tok < XT; tok++) {
        float acc0 = b0, acc1 = b1;
#pragma unroll
        for (int r = 0; r < RK; r++) {
            float d = ds[tok][r];
            acc0 = fmaf(w0r[r], d, acc0);
            acc1 = fmaf(w1r[r], d, acc1);
        }
        float d0 = (acc0 > 20.f) ? acc0 : log1pf(__expf(acc0));
        float d1 = (acc1 > 20.f) ? acc1 : log1pf(__expf(acc1));
        g_delta[(size_t)(t0 + tok) * DI + e0] = d0;
        g_delta[(size_t)(t0 + tok) * DI + e1] = d1;
    }
}

// ---------------- chunked scan: pass A (local scan + decay product) -------
__global__ void __launch_bounds__(64) scanA_kernel(const float* __restrict__ A_log)
{
    int gw   = (blockIdx.x * 64 + threadIdx.x) >> 5;   // 0..8191
    int lane = threadIdx.x & 31;
    int n    = lane & 15;
    int c    = gw >> 9;                 // chunk
    int cw   = gw & 511;
    int ch   = cw * 2 + (lane >> 4);    // channel 0..1023
    int b    = ch >> 9;
    int e    = ch & (DI - 1);

    float a = -__expf(A_log[(size_t)e * NS + n]);
    const float* del = g_delta + (size_t)b * L_ * DI + e;
    const float* xcp = g_xc    + (size_t)b * L_ * DI + e;
    const float* bcp = g_bc    + (size_t)b * L_ * 32;

    float h = 0.f, P = 1.f;
    const int l0 = c * CL;
#pragma unroll 4
    for (int l = l0; l < l0 + CL; l++) {
        float d_ = __ldg(del + (size_t)l * DI);
        float x_ = __ldg(xcp + (size_t)l * DI);
        float Bv = __ldg(bcp + (size_t)l * 32 + n);
        float dA = __expf(d_ * a);
        h = fmaf(dA, h, d_ * Bv * x_);
        P *= dA;
    }
    int idx = c * ST_ + ch * NS + n;
    g_hloc[idx] = h;
    g_P[idx]    = P;
}

// ---------------- chunked scan: pass B (combine across chunks) -----------
__global__ void __launch_bounds__(256) scanB_kernel()
{
    int j = blockIdx.x * 256 + threadIdx.x;   // 0..16383
    float h = 0.f;
#pragma unroll
    for (int c = 0; c < NC; c++) {
        int idx = c * ST_ + j;
        g_hin[idx] = h;
        h = fmaf(g_P[idx], h, g_hloc[idx]);
    }
}

// ---------------- chunked scan: pass C (outputs with carried state) ------
__global__ void __launch_bounds__(64) scanC_kernel(
    const float* __restrict__ A_log, const float* __restrict__ Dp)
{
    int gw   = (blockIdx.x * 64 + threadIdx.x) >> 5;
    int lane = threadIdx.x & 31;
    int n    = lane & 15;
    int c    = gw >> 9;
    int cw   = gw & 511;
    int ch   = cw * 2 + (lane >> 4);
    int b    = ch >> 9;
    int e    = ch & (DI - 1);

    float a  = -__expf(A_log[(size_t)e * NS + n]);
    float dp = Dp[e];
    const float* del = g_delta + (size_t)b * L_ * DI + e;
    const float* xcp = g_xc    + (size_t)b * L_ * DI + e;
    const float* zp  = g_z     + (size_t)b * L_ * DI + e;
    float*       yp  = g_y     + (size_t)b * L_ * DI + e;
    const float* bcp = g_bc    + (size_t)b * L_ * 32;

    float h = g_hin[c * ST_ + ch * NS + n];
    const int l0 = c * CL;
#pragma unroll 2
    for (int l = l0; l < l0 + CL; l++) {
        float d_ = __ldg(del + (size_t)l * DI);
        float x_ = __ldg(xcp + (size_t)l * DI);
        float Bv = __ldg(bcp + (size_t)l * 32 + n);
        float Cv = __ldg(bcp + (size_t)l * 32 + 16 + n);
        float dA = __expf(d_ * a);
        h = fmaf(dA, h, d_ * Bv * x_);
        float p = h * Cv;
        p += __shfl_xor_sync(0xffffffffu, p, 1);
        p += __shfl_xor_sync(0xffffffffu, p, 2);
        p += __shfl_xor_sync(0xffffffffu, p, 4);
        p += __shfl_xor_sync(0xffffffffu, p, 8);
        if (n == 0) {
            float zv = zp[(size_t)l * DI];                 // already silu(z)
            yp[(size_t)l * DI] = (p + x_ * dp) * zv;
        }
    }
}

// ---------------- host orchestration (launches only) ----------------------
extern "C" void kernel_launch(void* const* d_in, const int* in_sizes, int n_in,
                              void* d_out, int out_size)
{
    const float* x    = (const float*)d_in[0];
    const float* lnw  = (const float*)d_in[1];
    const float* lnb  = (const float*)d_in[2];
    const float* ipw  = (const float*)d_in[3];
    const float* cw   = (const float*)d_in[4];
    const float* cb   = (const float*)d_in[5];
    const float* xpw  = (const float*)d_in[6];
    const float* dpw  = (const float*)d_in[7];
    const float* dpb  = (const float*)d_in[8];
    const float* alog = (const float*)d_in[9];
    const float* dpar = (const float*)d_in[10];
    const float* opw  = (const float*)d_in[11];
    float* out = (float*)d_out;

    for (int ly = 0; ly < 2; ly++) {
        ln_kernel<<<T_, 256>>>(x, ly, lnw + (size_t)ly * DM, lnb + (size_t)ly * DM);

        gemm_k<128, 1><<<dim3(1024 / 128, T_ / 128), 256>>>(
            ipw + (size_t)ly * 1024 * DM, DM, ly, x, out);

        conv_silu_kernel<<<(T_ * DI) / 256, 256>>>(
            cw + (size_t)ly * DI * 4, cb + (size_t)ly * DI);

        xproj_delta_kernel<<<T_ / XT, 256>>>(
            xpw + (size_t)ly * 48 * DI,
            dpw + (size_t)ly * DI * RK,
            dpb + (size_t)ly * DI);

        scanA_kernel<<<(NC * 512) / 2, 64>>>(alog + (size_t)ly * DI * NS);
        scanB_kernel<<<ST_ / 256, 256>>>();
        scanC_kernel<<<(NC * 512) / 2, 64>>>(alog + (size_t)ly * DI * NS,
                                             dpar + (size_t)ly * DI);

        gemm_k<64, 2><<<dim3(DM / 128, T_ / 64), 256>>>(
            opw + (size_t)ly * DM * DI, DI, ly, x, out);
    }
}

// round 9
// speedup vs baseline: 1.0006x; 1.0006x over previous
#include <cuda_runtime.h>

// Problem constants
#define B_   2
#define L_   2048
#define DM   256      // d_model
#define DI   512      // d_inner
#define NS   16       // d_state
#define RK   16       // dt_rank
#define T_   (B_*L_)  // 4096 tokens
#define NC   16       // scan chunks
#define CL   128      // chunk length (NC*CL == L_)
#define ST_  (B_*DI*NS)  // 16384 state slots

// ---------------- scratch (device globals, no allocation) ----------------
__device__ float g_h[T_ * DM];       // layernorm output
__device__ float g_xi[T_ * DI];      // in_proj first half
__device__ float g_z[T_ * DI];       // silu(in_proj second half)
__device__ float g_xc[T_ * DI];      // conv + silu output
__device__ float g_bc[T_ * 32];      // x_proj B|C (16+16)
__device__ float g_delta[T_ * DI];   // softplus(dt @ dpw + dpb)
__device__ float g_y[T_ * DI];       // scan output (post gating)
__device__ float g_x1[T_ * DM];      // inter-layer residual stream
__device__ float g_hloc[NC * ST_];   // chunk-local end state (h_in = 0)
__device__ float g_P[NC * ST_];      // chunk decay products
__device__ float g_hin[NC * ST_];    // carried-in state per chunk

// ---------------- layernorm: one block (256 thr) per token ----------------
__global__ void __launch_bounds__(256) ln_kernel(
    const float* __restrict__ x0, int layer,
    const float* __restrict__ w, const float* __restrict__ b)
{
    const float* xin = layer ? g_x1 : x0;
    int t = blockIdx.x;
    int d = threadIdx.x;
    float v = xin[(size_t)t * DM + d];
    float s = v, s2 = v * v;
#pragma unroll
    for (int m = 16; m; m >>= 1) {
        s  += __shfl_xor_sync(0xffffffffu, s,  m);
        s2 += __shfl_xor_sync(0xffffffffu, s2, m);
    }
    __shared__ float ss[8], ss2[8];
    int wid = d >> 5, ln = d & 31;
    if (ln == 0) { ss[wid] = s; ss2[wid] = s2; }
    __syncthreads();
    float tot = 0.f, tot2 = 0.f;
#pragma unroll
    for (int i = 0; i < 8; i++) { tot += ss[i]; tot2 += ss2[i]; }
    float mu  = tot * (1.f / DM);
    float var = tot2 * (1.f / DM) - mu * mu;
    float r   = rsqrtf(var + 1e-5f);
    g_h[(size_t)t * DM + d] = (v - mu) * r * w[d] + b[d];
}

// ---------------- SGEMM NT: C[m][n] = dot(A[m,:], Bw[n,:]) ----------------
// BM x 128 tile, BK=8, 256 threads, (BM/16) x 8 microtile, float4 smem reads,
// register-staged double buffering.
// EPI 1: in_proj (A = g_h, N=1024): n<512 -> g_xi ; n>=512 -> silu -> g_z
// EPI 2: out_proj + residual (A = g_y, N=256)
template <int BM, int EPI>
__global__ void __launch_bounds__(256) gemm_k(
    const float* __restrict__ Bw, const int K,
    const int layer, const float* __restrict__ x0, float* __restrict__ dout)
{
    constexpr int TM = BM / 16;
    __shared__ float As[2][8][BM];
    __shared__ float Bs[2][8][128];

    const int tid = threadIdx.x;
    const int tx = tid & 15, ty = tid >> 4;
    const int bm = blockIdx.y * BM, bn = blockIdx.x * 128;
    const float* Aq = (EPI == 1) ? g_h : g_y;

    // global->reg load mapping
    int ar, ak;
    if (BM == 128) { ar = tid >> 1; ak = (tid & 1) * 4; }
    else           { ar = tid >> 2; ak = (tid & 3) * 2; }
    const int br = tid >> 1;
    const int bk = (tid & 1) * 4;
    const float* aptr = Aq + (size_t)(bm + ar) * K + ak;
    const float* bptr = Bw + (size_t)(bn + br) * K + bk;

    float acc[TM][8];
#pragma unroll
    for (int i = 0; i < TM; i++)
#pragma unroll
        for (int j = 0; j < 8; j++) acc[i][j] = 0.f;

    float ra[4];
    float4 rb;

    // prefetch k-tile 0
    if (BM == 128) {
        float4 v = *(const float4*)(aptr);
        ra[0] = v.x; ra[1] = v.y; ra[2] = v.z; ra[3] = v.w;
    } else {
        float2 v = *(const float2*)(aptr);
        ra[0] = v.x; ra[1] = v.y;
    }
    rb = *(const float4*)(bptr);
    if (BM == 128) {
        As[0][ak + 0][ar] = ra[0]; As[0][ak + 1][ar] = ra[1];
        As[0][ak + 2][ar] = ra[2]; As[0][ak + 3][ar] = ra[3];
    } else {
        As[0][ak + 0][ar] = ra[0]; As[0][ak + 1][ar] = ra[1];
    }
    Bs[0][bk + 0][br] = rb.x; Bs[0][bk + 1][br] = rb.y;
    Bs[0][bk + 2][br] = rb.z; Bs[0][bk + 3][br] = rb.w;
    __syncthreads();

    const int nt = K / 8;
    int cur = 0;
    for (int kt = 0; kt < nt; kt++) {
        if (kt + 1 < nt) {
            int k0 = (kt + 1) * 8;
            if (BM == 128) {
                float4 v = *(const float4*)(aptr + k0);
                ra[0] = v.x; ra[1] = v.y; ra[2] = v.z; ra[3] = v.w;
            } else {
                float2 v = *(const float2*)(aptr + k0);
                ra[0] = v.x; ra[1] = v.y;
            }
            rb = *(const float4*)(bptr + k0);
        }
#pragma unroll
        for (int kk = 0; kk < 8; kk++) {
            float av[TM], bv[8];
            float4 t0 = *(const float4*)&As[cur][kk][ty * 4];
            av[0] = t0.x; av[1] = t0.y; av[2] = t0.z; av[3] = t0.w;
            if (TM == 8) {
                float4 t1 = *(const float4*)&As[cur][kk][64 + ty * 4];
                av[4] = t1.x; av[5] = t1.y; av[6] = t1.z; av[7] = t1.w;
            }
            float4 u0 = *(const float4*)&Bs[cur][kk][tx * 4];
            float4 u1 = *(const float4*)&Bs[cur][kk][64 + tx * 4];
            bv[0] = u0.x; bv[1] = u0.y; bv[2] = u0.z; bv[3] = u0.w;
            bv[4] = u1.x; bv[5] = u1.y; bv[6] = u1.z; bv[7] = u1.w;
#pragma unroll
            for (int i = 0; i < TM; i++)
#pragma unroll
                for (int j = 0; j < 8; j++)
                    acc[i][j] = fmaf(av[i], bv[j], acc[i][j]);
        }
        if (kt + 1 < nt) {
            int nb = cur ^ 1;
            if (BM == 128) {
                As[nb][ak + 0][ar] = ra[0]; As[nb][ak + 1][ar] = ra[1];
                As[nb][ak + 2][ar] = ra[2]; As[nb][ak + 3][ar] = ra[3];
            } else {
                As[nb][ak + 0][ar] = ra[0]; As[nb][ak + 1][ar] = ra[1];
            }
            Bs[nb][bk + 0][br] = rb.x; Bs[nb][bk + 1][br] = rb.y;
            Bs[nb][bk + 2][br] = rb.z; Bs[nb][bk + 3][br] = rb.w;
            __syncthreads();
            cur = nb;
        }
    }

    // epilogue
#pragma unroll
    for (int i = 0; i < TM; i++) {
        int m;
        if (BM == 128) m = bm + (i >> 2) * 64 + ty * 4 + (i & 3);
        else           m = bm + ty * 4 + i;
        float4 v0, v1;
        v0.x = acc[i][0]; v0.y = acc[i][1]; v0.z = acc[i][2]; v0.w = acc[i][3];
        v1.x = acc[i][4]; v1.y = acc[i][5]; v1.z = acc[i][6]; v1.w = acc[i][7];
        int n0 = bn + tx * 4;
        int n1 = bn + 64 + tx * 4;
        if (EPI == 1) {
            if (bn < 512) {
                *(float4*)&g_xi[(size_t)m * DI + n0] = v0;
                *(float4*)&g_xi[(size_t)m * DI + n1] = v1;
            } else {
                v0.x = v0.x / (1.f + __expf(-v0.x));
                v0.y = v0.y / (1.f + __expf(-v0.y));
                v0.z = v0.z / (1.f + __expf(-v0.z));
                v0.w = v0.w / (1.f + __expf(-v0.w));
                v1.x = v1.x / (1.f + __expf(-v1.x));
                v1.y = v1.y / (1.f + __expf(-v1.y));
                v1.z = v1.z / (1.f + __expf(-v1.z));
                v1.w = v1.w / (1.f + __expf(-v1.w));
                *(float4*)&g_z[(size_t)m * DI + (n0 - 512)] = v0;
                *(float4*)&g_z[(size_t)m * DI + (n1 - 512)] = v1;
            }
        } else {
            const float* res = layer ? g_x1 : x0;
            float*       o   = layer ? dout : g_x1;
            float4 r0 = *(const float4*)&res[(size_t)m * DM + n0];
            float4 r1 = *(const float4*)&res[(size_t)m * DM + n1];
            v0.x += r0.x; v0.y += r0.y; v0.z += r0.z; v0.w += r0.w;
            v1.x += r1.x; v1.y += r1.y; v1.z += r1.z; v1.w += r1.w;
            *(float4*)&o[(size_t)m * DM + n0] = v0;
            *(float4*)&o[(size_t)m * DM + n1] = v1;
        }
    }
}

// ---------------- depthwise causal conv (k=4) + bias + silu ----------------
__global__ void __launch_bounds__(256) conv_silu_kernel(
    const float* __restrict__ cw, const float* __restrict__ cb)
{
    int idx = blockIdx.x * blockDim.x + threadIdx.x;   // over T_*DI
    int e = idx & (DI - 1);
    int t = idx >> 9;
    int l = t & (L_ - 1);
    float acc = cb[e];
    float w0 = cw[e * 4 + 0], w1 = cw[e * 4 + 1];
    float w2 = cw[e * 4 + 2], w3 = cw[e * 4 + 3];
    const float* base = g_xi + (size_t)t * DI + e;
    if (l >= 3) acc = fmaf(w0, base[-3 * DI], acc);
    if (l >= 2) acc = fmaf(w1, base[-2 * DI], acc);
    if (l >= 1) acc = fmaf(w2, base[-1 * DI], acc);
    acc = fmaf(w3, base[0], acc);
    g_xc[idx] = acc / (1.f + __expf(-acc));
}

// ---------------- fused x_proj (N=48) + delta --------------------------
// One block = 16 tokens. Stage 1: xc tile -> smem. Stage 2: dbl = xc @ xpw^T
// (2n x 2tok register blocking). Stage 3: delta = softplus(dt @ dpw^T + dpb).
#define XT 16
__global__ void __launch_bounds__(256) xproj_delta_kernel(
    const float* __restrict__ xpw,   // [48][512]
    const float* __restrict__ dpw,   // [512][16]
    const float* __restrict__ dpb)   // [512]
{
    __shared__ float xs[XT][DI];     // 32 KB
    __shared__ float ws[64][49];     // transposed weight chunk (padded)
    __shared__ float ds[XT][RK];     // dt
    const int tid = threadIdx.x;
    const int t0 = blockIdx.x * XT;

    // stage 1
    {
        const float4* src = (const float4*)(g_xc + (size_t)t0 * DI);
        float4* dst = (float4*)(&xs[0][0]);
#pragma unroll
        for (int i = 0; i < 8; i++) dst[tid + 256 * i] = src[tid + 256 * i];
    }
    __syncthreads();

    // stage 2
    const int ng = tid % 24;
    const int tg = tid / 24;
    const bool act = tg < 8;
    const int n0 = ng * 2, ta = tg * 2, tb = ta + 1;
    float a00 = 0.f, a01 = 0.f, a10 = 0.f, a11 = 0.f;

    for (int k0 = 0; k0 < DI; k0 += 64) {
#pragma unroll
        for (int j = 0; j < 3; j++) {
            int f = tid + 256 * j;
            int n = f >> 4, kk = (f & 15) * 4;
            float4 w4 = *(const float4*)(xpw + (size_t)n * DI + k0 + kk);
            ws[kk + 0][n] = w4.x; ws[kk + 1][n] = w4.y;
            ws[kk + 2][n] = w4.z; ws[kk + 3][n] = w4.w;
        }
        __syncthreads();
        if (act) {
#pragma unroll 16
            for (int k = 0; k < 64; k++) {
                float w0 = ws[k][n0], w1 = ws[k][n0 + 1];
                float xa = xs[ta][k0 + k], xb = xs[tb][k0 + k];
                a00 = fmaf(w0, xa, a00);
                a01 = fmaf(w1, xa, a01);
                a10 = fmaf(w0, xb, a10);
                a11 = fmaf(w1, xb, a11);
            }
        }
        __syncthreads();
    }
    if (act) {
        if (n0 < RK) { ds[ta][n0] = a00; ds[tb][n0] = a10; }
        else { g_bc[(size_t)(t0 + ta) * 32 + n0 - RK] = a00;
               g_bc[(size_t)(t0 + tb) * 32 + n0 - RK] = a10; }
        int n1 = n0 + 1;
        if (n1 < RK) { ds[ta][n1] = a01; ds[tb][n1] = a11; }
        else { g_bc[(size_t)(t0 + ta) * 32 + n1 - RK] = a01;
               g_bc[(size_t)(t0 + tb) * 32 + n1 - RK] = a11; }
    }
    __syncthreads();

    // stage 3: delta for e0 = tid, e1 = tid + 256
    const int e0 = tid, e1 = tid + 256;
    float w0r[16], w1r[16];
#pragma unroll
    for (int q = 0; q < 4; q++) {
        float4 v = *(const float4*)(dpw + (size_t)e0 * RK + q * 4);
        w0r[q * 4 + 0] = v.x; w0r[q * 4 + 1] = v.y;
        w0r[q * 4 + 2] = v.z; w0r[q * 4 + 3] = v.w;
        float4 u = *(const float4*)(dpw + (size_t)e1 * RK + q * 4);
        w1r[q * 4 + 0] = u.x; w1r[q * 4 + 1] = u.y;
        w1r[q * 4 + 2] = u.z; w1r[q * 4 + 3] = u.w;
    }
    float b0 = dpb[e0], b1 = dpb[e1];
#pragma unroll
    for (int tok = 0; tok < XT; tok++) {
        float acc0 = b0, acc1 = b1;
#pragma unroll
        for (int r = 0; r < RK; r++) {
            float d = ds[tok][r];
            acc0 = fmaf(w0r[r], d, acc0);
            acc1 = fmaf(w1r[r], d, acc1);
        }
        float d0 = (acc0 > 20.f) ? acc0 : log1pf(__expf(acc0));
        float d1 = (acc1 > 20.f) ? acc1 : log1pf(__expf(acc1));
        g_delta[(size_t)(t0 + tok) * DI + e0] = d0;
        g_delta[(size_t)(t0 + tok) * DI + e1] = d1;
    }
}

// ---------------- chunked scan: pass A (local scan + decay product) -------
__global__ void __launch_bounds__(64) scanA_kernel(const float* __restrict__ A_log)
{
    int gw   = (blockIdx.x * 64 + threadIdx.x) >> 5;   // 0..8191
    int lane = threadIdx.x & 31;
    int n    = lane & 15;
    int c    = gw >> 9;                 // chunk
    int cw   = gw & 511;
    int ch   = cw * 2 + (lane >> 4);    // channel 0..1023
    int b    = ch >> 9;
    int e    = ch & (DI - 1);

    float a = -__expf(A_log[(size_t)e * NS + n]);
    const float* del = g_delta + (size_t)b * L_ * DI + e;
    const float* xcp = g_xc    + (size_t)b * L_ * DI + e;
    const float* bcp = g_bc    + (size_t)b * L_ * 32;

    float h = 0.f, P = 1.f;
    const int l0 = c * CL;
#pragma unroll 4
    for (int l = l0; l < l0 + CL; l++) {
        float d_ = __ldg(del + (size_t)l * DI);
        float x_ = __ldg(xcp + (size_t)l * DI);
        float Bv = __ldg(bcp + (size_t)l * 32 + n);
        float dA = __expf(d_ * a);
        h = fmaf(dA, h, d_ * Bv * x_);
        P *= dA;
    }
    int idx = c * ST_ + ch * NS + n;
    g_hloc[idx] = h;
    g_P[idx]    = P;
}

// ---------------- chunked scan: pass B (combine across chunks) -----------
__global__ void __launch_bounds__(256) scanB_kernel()
{
    int j = blockIdx.x * 256 + threadIdx.x;   // 0..16383
    float h = 0.f;
#pragma unroll
    for (int c = 0; c < NC; c++) {
        int idx = c * ST_ + j;
        g_hin[idx] = h;
        h = fmaf(g_P[idx], h, g_hloc[idx]);
    }
}

// ---------------- chunked scan: pass C (outputs with carried state) ------
__global__ void __launch_bounds__(64) scanC_kernel(
    const float* __restrict__ A_log, const float* __restrict__ Dp)
{
    int gw   = (blockIdx.x * 64 + threadIdx.x) >> 5;
    int lane = threadIdx.x & 31;
    int n    = lane & 15;
    int c    = gw >> 9;
    int cw   = gw & 511;
    int ch   = cw * 2 + (lane >> 4);
    int b    = ch >> 9;
    int e    = ch & (DI - 1);

    float a  = -__expf(A_log[(size_t)e * NS + n]);
    float dp = Dp[e];
    const float* del = g_delta + (size_t)b * L_ * DI + e;
    const float* xcp = g_xc    + (size_t)b * L_ * DI + e;
    const float* zp  = g_z     + (size_t)b * L_ * DI + e;
    float*       yp  = g_y     + (size_t)b * L_ * DI + e;
    const float* bcp = g_bc    + (size_t)b * L_ * 32;

    float h = g_hin[c * ST_ + ch * NS + n];
    const int l0 = c * CL;
#pragma unroll 2
    for (int l = l0; l < l0 + CL; l++) {
        float d_ = __ldg(del + (size_t)l * DI);
        float x_ = __ldg(xcp + (size_t)l * DI);
        float Bv = __ldg(bcp + (size_t)l * 32 + n);
        float Cv = __ldg(bcp + (size_t)l * 32 + 16 + n);
        float dA = __expf(d_ * a);
        h = fmaf(dA, h, d_ * Bv * x_);
        float p = h * Cv;
        p += __shfl_xor_sync(0xffffffffu, p, 1);
        p += __shfl_xor_sync(0xffffffffu, p, 2);
        p += __shfl_xor_sync(0xffffffffu, p, 4);
        p += __shfl_xor_sync(0xffffffffu, p, 8);
        if (n == 0) {
            float zv = zp[(size_t)l * DI];                 // already silu(z)
            yp[(size_t)l * DI] = (p + x_ * dp) * zv;
        }
    }
}

// ---------------- host orchestration (launches only) ----------------------
extern "C" void kernel_launch(void* const* d_in, const int* in_sizes, int n_in,
                              void* d_out, int out_size)
{
    const float* x    = (const float*)d_in[0];
    const float* lnw  = (const float*)d_in[1];
    const float* lnb  = (const float*)d_in[2];
    const float* ipw  = (const float*)d_in[3];
    const float* cw   = (const float*)d_in[4];
    const float* cb   = (const float*)d_in[5];
    const float* xpw  = (const float*)d_in[6];
    const float* dpw  = (const float*)d_in[7];
    const float* dpb  = (const float*)d_in[8];
    const float* alog = (const float*)d_in[9];
    const float* dpar = (const float*)d_in[10];
    const float* opw  = (const float*)d_in[11];
    float* out = (float*)d_out;

    for (int ly = 0; ly < 2; ly++) {
        ln_kernel<<<T_, 256>>>(x, ly, lnw + (size_t)ly * DM, lnb + (size_t)ly * DM);

        gemm_k<128, 1><<<dim3(1024 / 128, T_ / 128), 256>>>(
            ipw + (size_t)ly * 1024 * DM, DM, ly, x, out);

        conv_silu_kernel<<<(T_ * DI) / 256, 256>>>(
            cw + (size_t)ly * DI * 4, cb + (size_t)ly * DI);

        xproj_delta_kernel<<<T_ / XT, 256>>>(
            xpw + (size_t)ly * 48 * DI,
            dpw + (size_t)ly * DI * RK,
            dpb + (size_t)ly * DI);

        scanA_kernel<<<(NC * 512) / 2, 64>>>(alog + (size_t)ly * DI * NS);
        scanB_kernel<<<ST_ / 256, 256>>>();
        scanC_kernel<<<(NC * 512) / 2, 64>>>(alog + (size_t)ly * DI * NS,
                                             dpar + (size_t)ly * DI);

        gemm_k<64, 2><<<dim3(DM / 128, T_ / 64), 256>>>(
            opw + (size_t)ly * DM * DI, DI, ly, x, out);
    }
}

// round 10
// speedup vs baseline: 1.0175x; 1.0169x over previous
#include <cuda_runtime.h>

// Problem constants
#define B_   2
#define L_   2048
#define DM   256      // d_model
#define DI   512      // d_inner
#define NS   16       // d_state
#define RK   16       // dt_rank
#define T_   (B_*L_)  // 4096 tokens
#define NC   16       // scan chunks
#define CL   128      // chunk length (NC*CL == L_)
#define ST_  (B_*DI*NS)  // 16384 state slots

// ---------------- scratch (device globals, no allocation) ----------------
__device__ float g_h[T_ * DM];       // layernorm output
__device__ float g_xi[T_ * DI];      // in_proj first half
__device__ float g_z[T_ * DI];       // silu(in_proj second half)
__device__ float g_xc[T_ * DI];      // conv + silu output
__device__ float g_bc[T_ * 32];      // x_proj B|C (16+16)
__device__ float g_delta[T_ * DI];   // softplus(dt @ dpw + dpb)
__device__ float g_y[T_ * DI];       // scan output (post gating)
__device__ float g_x1[T_ * DM];      // inter-layer residual stream
__device__ float g_hloc[NC * ST_];   // chunk-local end state (h_in = 0)
__device__ float g_P[NC * ST_];      // chunk decay products
__device__ float g_hin[NC * ST_];    // carried-in state per chunk

// ---------------- layernorm: one block (256 thr) per token ----------------
__global__ void __launch_bounds__(256) ln_kernel(
    const float* __restrict__ x0, int layer,
    const float* __restrict__ w, const float* __restrict__ b)
{
    const float* xin = layer ? g_x1 : x0;
    int t = blockIdx.x;
    int d = threadIdx.x;
    float v = xin[(size_t)t * DM + d];
    float s = v, s2 = v * v;
#pragma unroll
    for (int m = 16; m; m >>= 1) {
        s  += __shfl_xor_sync(0xffffffffu, s,  m);
        s2 += __shfl_xor_sync(0xffffffffu, s2, m);
    }
    __shared__ float ss[8], ss2[8];
    int wid = d >> 5, ln = d & 31;
    if (ln == 0) { ss[wid] = s; ss2[wid] = s2; }
    __syncthreads();
    float tot = 0.f, tot2 = 0.f;
#pragma unroll
    for (int i = 0; i < 8; i++) { tot += ss[i]; tot2 += ss2[i]; }
    float mu  = tot * (1.f / DM);
    float var = tot2 * (1.f / DM) - mu * mu;
    float r   = rsqrtf(var + 1e-5f);
    g_h[(size_t)t * DM + d] = (v - mu) * r * w[d] + b[d];
}

// ---------------- SGEMM NT: C[m][n] = dot(A[m,:], Bw[n,:]) ----------------
// BM x 128 tile, BK=8, 256 threads, (BM/16) x 8 microtile, float4 smem reads,
// register-staged double buffering.
// EPI 1: in_proj (A = g_h, N=1024): n<512 -> g_xi ; n>=512 -> silu -> g_z
// EPI 2: out_proj + residual (A = g_y, N=256)
template <int BM, int EPI>
__global__ void __launch_bounds__(256) gemm_k(
    const float* __restrict__ Bw, const int K,
    const int layer, const float* __restrict__ x0, float* __restrict__ dout)
{
    constexpr int TM = BM / 16;
    __shared__ float As[2][8][BM];
    __shared__ float Bs[2][8][128];

    const int tid = threadIdx.x;
    const int tx = tid & 15, ty = tid >> 4;
    const int bm = blockIdx.y * BM, bn = blockIdx.x * 128;
    const float* Aq = (EPI == 1) ? g_h : g_y;

    // global->reg load mapping
    int ar, ak;
    if (BM == 128) { ar = tid >> 1; ak = (tid & 1) * 4; }
    else           { ar = tid >> 2; ak = (tid & 3) * 2; }
    const int br = tid >> 1;
    const int bk = (tid & 1) * 4;
    const float* aptr = Aq + (size_t)(bm + ar) * K + ak;
    const float* bptr = Bw + (size_t)(bn + br) * K + bk;

    float acc[TM][8];
#pragma unroll
    for (int i = 0; i < TM; i++)
#pragma unroll
        for (int j = 0; j < 8; j++) acc[i][j] = 0.f;

    float ra[4];
    float4 rb;

    // prefetch k-tile 0
    if (BM == 128) {
        float4 v = *(const float4*)(aptr);
        ra[0] = v.x; ra[1] = v.y; ra[2] = v.z; ra[3] = v.w;
    } else {
        float2 v = *(const float2*)(aptr);
        ra[0] = v.x; ra[1] = v.y;
    }
    rb = *(const float4*)(bptr);
    if (BM == 128) {
        As[0][ak + 0][ar] = ra[0]; As[0][ak + 1][ar] = ra[1];
        As[0][ak + 2][ar] = ra[2]; As[0][ak + 3][ar] = ra[3];
    } else {
        As[0][ak + 0][ar] = ra[0]; As[0][ak + 1][ar] = ra[1];
    }
    Bs[0][bk + 0][br] = rb.x; Bs[0][bk + 1][br] = rb.y;
    Bs[0][bk + 2][br] = rb.z; Bs[0][bk + 3][br] = rb.w;
    __syncthreads();

    const int nt = K / 8;
    int cur = 0;
    for (int kt = 0; kt < nt; kt++) {
        if (kt + 1 < nt) {
            int k0 = (kt + 1) * 8;
            if (BM == 128) {
                float4 v = *(const float4*)(aptr + k0);
                ra[0] = v.x; ra[1] = v.y; ra[2] = v.z; ra[3] = v.w;
            } else {
                float2 v = *(const float2*)(aptr + k0);
                ra[0] = v.x; ra[1] = v.y;
            }
            rb = *(const float4*)(bptr + k0);
        }
#pragma unroll
        for (int kk = 0; kk < 8; kk++) {
            float av[TM], bv[8];
            float4 t0 = *(const float4*)&As[cur][kk][ty * 4];
            av[0] = t0.x; av[1] = t0.y; av[2] = t0.z; av[3] = t0.w;
            if (TM == 8) {
                float4 t1 = *(const float4*)&As[cur][kk][64 + ty * 4];
                av[4] = t1.x; av[5] = t1.y; av[6] = t1.z; av[7] = t1.w;
            }
            float4 u0 = *(const float4*)&Bs[cur][kk][tx * 4];
            float4 u1 = *(const float4*)&Bs[cur][kk][64 + tx * 4];
            bv[0] = u0.x; bv[1] = u0.y; bv[2] = u0.z; bv[3] = u0.w;
            bv[4] = u1.x; bv[5] = u1.y; bv[6] = u1.z; bv[7] = u1.w;
#pragma unroll
            for (int i = 0; i < TM; i++)
#pragma unroll
                for (int j = 0; j < 8; j++)
                    acc[i][j] = fmaf(av[i], bv[j], acc[i][j]);
        }
        if (kt + 1 < nt) {
            int nb = cur ^ 1;
            if (BM == 128) {
                As[nb][ak + 0][ar] = ra[0]; As[nb][ak + 1][ar] = ra[1];
                As[nb][ak + 2][ar] = ra[2]; As[nb][ak + 3][ar] = ra[3];
            } else {
                As[nb][ak + 0][ar] = ra[0]; As[nb][ak + 1][ar] = ra[1];
            }
            Bs[nb][bk + 0][br] = rb.x; Bs[nb][bk + 1][br] = rb.y;
            Bs[nb][bk + 2][br] = rb.z; Bs[nb][bk + 3][br] = rb.w;
            __syncthreads();
            cur = nb;
        }
    }

    // epilogue
#pragma unroll
    for (int i = 0; i < TM; i++) {
        int m;
        if (BM == 128) m = bm + (i >> 2) * 64 + ty * 4 + (i & 3);
        else           m = bm + ty * 4 + i;
        float4 v0, v1;
        v0.x = acc[i][0]; v0.y = acc[i][1]; v0.z = acc[i][2]; v0.w = acc[i][3];
        v1.x = acc[i][4]; v1.y = acc[i][5]; v1.z = acc[i][6]; v1.w = acc[i][7];
        int n0 = bn + tx * 4;
        int n1 = bn + 64 + tx * 4;
        if (EPI == 1) {
            if (bn < 512) {
                *(float4*)&g_xi[(size_t)m * DI + n0] = v0;
                *(float4*)&g_xi[(size_t)m * DI + n1] = v1;
            } else {
                v0.x = v0.x / (1.f + __expf(-v0.x));
                v0.y = v0.y / (1.f + __expf(-v0.y));
                v0.z = v0.z / (1.f + __expf(-v0.z));
                v0.w = v0.w / (1.f + __expf(-v0.w));
                v1.x = v1.x / (1.f + __expf(-v1.x));
                v1.y = v1.y / (1.f + __expf(-v1.y));
                v1.z = v1.z / (1.f + __expf(-v1.z));
                v1.w = v1.w / (1.f + __expf(-v1.w));
                *(float4*)&g_z[(size_t)m * DI + (n0 - 512)] = v0;
                *(float4*)&g_z[(size_t)m * DI + (n1 - 512)] = v1;
            }
        } else {
            const float* res = layer ? g_x1 : x0;
            float*       o   = layer ? dout : g_x1;
            float4 r0 = *(const float4*)&res[(size_t)m * DM + n0];
            float4 r1 = *(const float4*)&res[(size_t)m * DM + n1];
            v0.x += r0.x; v0.y += r0.y; v0.z += r0.z; v0.w += r0.w;
            v1.x += r1.x; v1.y += r1.y; v1.z += r1.z; v1.w += r1.w;
            *(float4*)&o[(size_t)m * DM + n0] = v0;
            *(float4*)&o[(size_t)m * DM + n1] = v1;
        }
    }
}

// ---------------- depthwise causal conv (k=4) + bias + silu ----------------
__global__ void __launch_bounds__(256) conv_silu_kernel(
    const float* __restrict__ cw, const float* __restrict__ cb)
{
    int idx = blockIdx.x * blockDim.x + threadIdx.x;   // over T_*DI
    int e = idx & (DI - 1);
    int t = idx >> 9;
    int l = t & (L_ - 1);
    float acc = cb[e];
    float w0 = cw[e * 4 + 0], w1 = cw[e * 4 + 1];
    float w2 = cw[e * 4 + 2], w3 = cw[e * 4 + 3];
    const float* base = g_xi + (size_t)t * DI + e;
    if (l >= 3) acc = fmaf(w0, base[-3 * DI], acc);
    if (l >= 2) acc = fmaf(w1, base[-2 * DI], acc);
    if (l >= 1) acc = fmaf(w2, base[-1 * DI], acc);
    acc = fmaf(w3, base[0], acc);
    g_xc[idx] = acc / (1.f + __expf(-acc));
}

// ---------------- fused x_proj (N=48) + delta --------------------------
// One block = 16 tokens. Stage 1: xc tile -> smem. Stage 2: dbl = xc @ xpw^T
// (2n x 2tok register blocking). Stage 3: delta = softplus(dt @ dpw^T + dpb).
#define XT 16
__global__ void __launch_bounds__(256) xproj_delta_kernel(
    const float* __restrict__ xpw,   // [48][512]
    const float* __restrict__ dpw,   // [512][16]
    const float* __restrict__ dpb)   // [512]
{
    __shared__ float xs[XT][DI];     // 32 KB
    __shared__ float ws[64][49];     // transposed weight chunk (padded)
    __shared__ float ds[XT][RK];     // dt
    const int tid = threadIdx.x;
    const int t0 = blockIdx.x * XT;

    // stage 1
    {
        const float4* src = (const float4*)(g_xc + (size_t)t0 * DI);
        float4* dst = (float4*)(&xs[0][0]);
#pragma unroll
        for (int i = 0; i < 8; i++) dst[tid + 256 * i] = src[tid + 256 * i];
    }
    __syncthreads();

    // stage 2
    const int ng = tid % 24;
    const int tg = tid / 24;
    const bool act = tg < 8;
    const int n0 = ng * 2, ta = tg * 2, tb = ta + 1;
    float a00 = 0.f, a01 = 0.f, a10 = 0.f, a11 = 0.f;

    for (int k0 = 0; k0 < DI; k0 += 64) {
#pragma unroll
        for (int j = 0; j < 3; j++) {
            int f = tid + 256 * j;
            int n = f >> 4, kk = (f & 15) * 4;
            float4 w4 = *(const float4*)(xpw + (size_t)n * DI + k0 + kk);
            ws[kk + 0][n] = w4.x; ws[kk + 1][n] = w4.y;
            ws[kk + 2][n] = w4.z; ws[kk + 3][n] = w4.w;
        }
        __syncthreads();
        if (act) {
#pragma unroll 16
            for (int k = 0; k < 64; k++) {
                float w0 = ws[k][n0], w1 = ws[k][n0 + 1];
                float xa = xs[ta][k0 + k], xb = xs[tb][k0 + k];
                a00 = fmaf(w0, xa, a00);
                a01 = fmaf(w1, xa, a01);
                a10 = fmaf(w0, xb, a10);
                a11 = fmaf(w1, xb, a11);
            }
        }
        __syncthreads();
    }
    if (act) {
        if (n0 < RK) { ds[ta][n0] = a00; ds[tb][n0] = a10; }
        else { g_bc[(size_t)(t0 + ta) * 32 + n0 - RK] = a00;
               g_bc[(size_t)(t0 + tb) * 32 + n0 - RK] = a10; }
        int n1 = n0 + 1;
        if (n1 < RK) { ds[ta][n1] = a01; ds[tb][n1] = a11; }
        else { g_bc[(size_t)(t0 + ta) * 32 + n1 - RK] = a01;
               g_bc[(size_t)(t0 + tb) * 32 + n1 - RK] = a11; }
    }
    __syncthreads();

    // stage 3: delta for e0 = tid, e1 = tid + 256
    const int e0 = tid, e1 = tid + 256;
    float w0r[16], w1r[16];
#pragma unroll
    for (int q = 0; q < 4; q++) {
        float4 v = *(const float4*)(dpw + (size_t)e0 * RK + q * 4);
        w0r[q * 4 + 0] = v.x; w0r[q * 4 + 1] = v.y;
        w0r[q * 4 + 2] = v.z; w0r[q * 4 + 3] = v.w;
        float4 u = *(const float4*)(dpw + (size_t)e1 * RK + q * 4);
        w1r[q * 4 + 0] = u.x; w1r[q * 4 + 1] = u.y;
        w1r[q * 4 + 2] = u.z; w1r[q * 4 + 3] = u.w;
    }
    float b0 = dpb[e0], b1 = dpb[e1];
#pragma unroll
    for (int tok = 0; tok < XT; tok++) {
        float acc0 = b0, acc1 = b1;
#pragma unroll
        for (int r = 0; r < RK; r++) {
            float d = ds[tok][r];
            acc0 = fmaf(w0r[r], d, acc0);
            acc1 = fmaf(w1r[r], d, acc1);
        }
        float d0 = (acc0 > 20.f) ? acc0 : log1pf(__expf(acc0));
        float d1 = (acc1 > 20.f) ? acc1 : log1pf(__expf(acc1));
        g_delta[(size_t)(t0 + tok) * DI + e0] = d0;
        g_delta[(size_t)(t0 + tok) * DI + e1] = d1;
    }
}

// ---------------- chunked scan: pass A (local scan + decay product) -------
__global__ void __launch_bounds__(64) scanA_kernel(const float* __restrict__ A_log)
{
    int gw   = (blockIdx.x * 64 + threadIdx.x) >> 5;   // 0..8191
    int lane = threadIdx.x & 31;
    int n    = lane & 15;
    int c    = gw >> 9;                 // chunk
    int cw   = gw & 511;
    int ch   = cw * 2 + (lane >> 4);    // channel 0..1023
    int b    = ch >> 9;
    int e    = ch & (DI - 1);

    float a = -__expf(A_log[(size_t)e * NS + n]);
    const float* del = g_delta + (size_t)b * L_ * DI + e;
    const float* xcp = g_xc    + (size_t)b * L_ * DI + e;
    const float* bcp = g_bc    + (size_t)b * L_ * 32;

    float h = 0.f, P = 1.f;
    const int l0 = c * CL;
#pragma unroll 4
    for (int l = l0; l < l0 + CL; l++) {
        float d_ = __ldg(del + (size_t)l * DI);
        float x_ = __ldg(xcp + (size_t)l * DI);
        float Bv = __ldg(bcp + (size_t)l * 32 + n);
        float dA = __expf(d_ * a);
        h = fmaf(dA, h, d_ * Bv * x_);
        P *= dA;
    }
    int idx = c * ST_ + ch * NS + n;
    g_hloc[idx] = h;
    g_P[idx]    = P;
}

// ---------------- chunked scan: pass B (combine across chunks) -----------
__global__ void __launch_bounds__(256) scanB_kernel()
{
    int j = blockIdx.x * 256 + threadIdx.x;   // 0..16383
    float h = 0.f;
#pragma unroll
    for (int c = 0; c < NC; c++) {
        int idx = c * ST_ + j;
        g_hin[idx] = h;
        h = fmaf(g_P[idx], h, g_hloc[idx]);
    }
}

// ---------------- chunked scan: pass C (outputs with carried state) ------
__global__ void __launch_bounds__(64) scanC_kernel(
    const float* __restrict__ A_log, const float* __restrict__ Dp)
{
    int gw   = (blockIdx.x * 64 + threadIdx.x) >> 5;
    int lane = threadIdx.x & 31;
    int n    = lane & 15;
    int c    = gw >> 9;
    int cw   = gw & 511;
    int ch   = cw * 2 + (lane >> 4);
    int b    = ch >> 9;
    int e    = ch & (DI - 1);

    float a  = -__expf(A_log[(size_t)e * NS + n]);
    float dp = Dp[e];
    const float* del = g_delta + (size_t)b * L_ * DI + e;
    const float* xcp = g_xc    + (size_t)b * L_ * DI + e;
    const float* zp  = g_z     + (size_t)b * L_ * DI + e;
    float*       yp  = g_y     + (size_t)b * L_ * DI + e;
    const float* bcp = g_bc    + (size_t)b * L_ * 32;

    float h = g_hin[c * ST_ + ch * NS + n];
    const int l0 = c * CL;
#pragma unroll 2
    for (int l = l0; l < l0 + CL; l++) {
        float d_ = __ldg(del + (size_t)l * DI);
        float x_ = __ldg(xcp + (size_t)l * DI);
        float Bv = __ldg(bcp + (size_t)l * 32 + n);
        float Cv = __ldg(bcp + (size_t)l * 32 + 16 + n);
        float dA = __expf(d_ * a);
        h = fmaf(dA, h, d_ * Bv * x_);
        float p = h * Cv;
        p += __shfl_xor_sync(0xffffffffu, p, 1);
        p += __shfl_xor_sync(0xffffffffu, p, 2);
        p += __shfl_xor_sync(0xffffffffu, p, 4);
        p += __shfl_xor_sync(0xffffffffu, p, 8);
        if (n == 0) {
            float zv = zp[(size_t)l * DI];                 // already silu(z)
            yp[(size_t)l * DI] = (p + x_ * dp) * zv;
        }
    }
}

// ---------------- host orchestration (launches only) ----------------------
extern "C" void kernel_launch(void* const* d_in, const int* in_sizes, int n_in,
                              void* d_out, int out_size)
{
    const float* x    = (const float*)d_in[0];
    const float* lnw  = (const float*)d_in[1];
    const float* lnb  = (const float*)d_in[2];
    const float* ipw  = (const float*)d_in[3];
    const float* cw   = (const float*)d_in[4];
    const float* cb   = (const float*)d_in[5];
    const float* xpw  = (const float*)d_in[6];
    const float* dpw  = (const float*)d_in[7];
    const float* dpb  = (const float*)d_in[8];
    const float* alog = (const float*)d_in[9];
    const float* dpar = (const float*)d_in[10];
    const float* opw  = (const float*)d_in[11];
    float* out = (float*)d_out;

    for (int ly = 0; ly < 2; ly++) {
        ln_kernel<<<T_, 256>>>(x, ly, lnw + (size_t)ly * DM, lnb + (size_t)ly * DM);

        gemm_k<128, 1><<<dim3(1024 / 128, T_ / 128), 256>>>(
            ipw + (size_t)ly * 1024 * DM, DM, ly, x, out);

        conv_silu_kernel<<<(T_ * DI) / 256, 256>>>(
            cw + (size_t)ly * DI * 4, cb + (size_t)ly * DI);

        xproj_delta_kernel<<<T_ / XT, 256>>>(
            xpw + (size_t)ly * 48 * DI,
            dpw + (size_t)ly * DI * RK,
            dpb + (size_t)ly * DI);

        scanA_kernel<<<(NC * 512) / 2, 64>>>(alog + (size_t)ly * DI * NS);
        scanB_kernel<<<ST_ / 256, 256>>>();
        scanC_kernel<<<(NC * 512) / 2, 64>>>(alog + (size_t)ly * DI * NS,
                                             dpar + (size_t)ly * DI);

        gemm_k<64, 2><<<dim3(DM / 128, T_ / 64), 256>>>(
            opw + (size_t)ly * DM * DI, DI, ly, x, out);
    }
}